// round 6
// baseline (speedup 1.0000x reference)
#include <cuda_runtime.h>
#include <cuda_bf16.h>

#define B_    32
#define H_    64
#define KVH_  8
#define D_    128
#define HID_  8192
#define CL_   1024
#define SP_   511
#define NTOT  10240

// ---------------- scratch ----------------
__device__ float    g_qkv[B_ * NTOT];     // fp32 qkv [b][n]
__device__ unsigned g_xhi[B_ * 4096];     // x hi bf16x2 [b][k/2]
__device__ unsigned g_xlo[B_ * 4096];
__device__ unsigned g_ahi[B_ * 4096];     // attn out hi bf16x2 [b][k/2]
__device__ unsigned g_alo[B_ * 4096];

// smem byte offsets (48 KB total)
#define SM_WHI 0
#define SM_WLO 16384
#define SM_BHI 32768
#define SM_BLO 40960
#define SM_TOT 49152

// ---------------- helpers ----------------
__device__ __forceinline__ void split2(float f0, float f1, unsigned& hi, unsigned& lo) {
    __nv_bfloat162 h = __floats2bfloat162_rn(f0, f1);
    unsigned hb = *reinterpret_cast<unsigned*>(&h);
    float h0 = __uint_as_float(hb << 16);
    float h1 = __uint_as_float(hb & 0xffff0000u);
    __nv_bfloat162 l = __floats2bfloat162_rn(f0 - h0, f1 - h1);
    hi = hb;
    lo = *reinterpret_cast<unsigned*>(&l);
}

__device__ __forceinline__ void ldsm4(unsigned& r0, unsigned& r1, unsigned& r2,
                                      unsigned& r3, unsigned addr) {
    asm volatile("ldmatrix.sync.aligned.m8n8.x4.shared.b16 {%0,%1,%2,%3}, [%4];"
                 : "=r"(r0), "=r"(r1), "=r"(r2), "=r"(r3) : "r"(addr));
}

__device__ __forceinline__ void mma16816(float* c, const unsigned* a,
                                         unsigned b0, unsigned b1) {
    asm volatile(
        "mma.sync.aligned.m16n8k16.row.col.f32.bf16.bf16.f32 "
        "{%0,%1,%2,%3}, {%4,%5,%6,%7}, {%8,%9}, {%0,%1,%2,%3};"
        : "+f"(c[0]), "+f"(c[1]), "+f"(c[2]), "+f"(c[3])
        : "r"(a[0]), "r"(a[1]), "r"(a[2]), "r"(a[3]), "r"(b0), "r"(b1));
}

// ---------------- x -> bf16 hi/lo ----------------
__global__ void cvt_x(const float* __restrict__ x) {
    int t = blockIdx.x * blockDim.x + threadIdx.x;      // 131072 pairs
    float f0 = x[2 * t], f1 = x[2 * t + 1];
    unsigned h, l;
    split2(f0, f1, h, l);
    g_xhi[t] = h;
    g_xlo[t] = l;
}

// ---------------- HMMA GEMM ----------------
// D[m = W-row][n = batch] = sum_k W[m][k] * B[n][k], written as C[n][m].
// BM=64 rows/CTA, 4 warps (warp = 16 rows x 32 batch), K=8192 chunked by 128.
// 3 bf16 passes: Whi*Bhi + Wlo*Bhi + Whi*Blo, fp32 accumulate.
__global__ __launch_bounds__(128)
void gemm_mma(int bsel,
              const float* __restrict__ W0, const float* __restrict__ W1,
              const float* __restrict__ W2,
              int nb1, int nb2,
              int csel, float* __restrict__ Cext, int ldc)
{
    extern __shared__ char smem[];
    unsigned sb = (unsigned)__cvta_generic_to_shared(smem);
    int tid = threadIdx.x, lane = tid & 31, wid = tid >> 5;

    int n0 = blockIdx.x * 64;
    const float* W; int wrow;
    if (n0 < nb1)      { W = W0; wrow = n0; }
    else if (n0 < nb2) { W = W1; wrow = n0 - nb1; }
    else               { W = W2; wrow = n0 - nb2; }

    const unsigned* __restrict__ Bh = bsel ? g_ahi : g_xhi;
    const unsigned* __restrict__ Bl = bsel ? g_alo : g_xlo;
    float* C = csel ? Cext : g_qkv;

    const float* wbase = W + (size_t)wrow * HID_;
    int sk = lane * 4;                       // k offset for W staging (0..124)

    // ldmatrix per-lane source descriptors
    int r0   = wid * 16;
    int arow = r0 + (lane & 7) + ((lane >> 3) & 1) * 8;
    int acs  = (lane >> 4) & 1;
    unsigned abase = (unsigned)(arow * 256);
    int arm  = arow & 7;
    int brow1 = (lane & 7) + ((lane >> 4) & 1) * 8;   // n rows 0..15
    int bcs   = (lane >> 3) & 1;
    int brow2 = brow1 + 16;                           // n rows 16..31

    float acc[4][4];
    #pragma unroll
    for (int i = 0; i < 4; ++i)
        #pragma unroll
        for (int j = 0; j < 4; ++j) acc[i][j] = 0.0f;

    for (int c = 0; c < 64; ++c) {
        int kc = c * 128;

        // ---- stage W (fp32 -> bf16 hi/lo, swizzled) ----
        #pragma unroll
        for (int i = 0; i < 16; ++i) {
            int row = wid + 4 * i;
            float4 w = *(const float4*)(wbase + (size_t)row * HID_ + kc + sk);
            unsigned h0, l0, h1, l1;
            split2(w.x, w.y, h0, l0);
            split2(w.z, w.w, h1, l1);
            unsigned seg = (unsigned)(sk >> 3);
            unsigned off = (unsigned)(row * 256) + ((seg ^ (unsigned)(row & 7)) << 4)
                         + ((unsigned)(sk & 4) << 1);
            *(uint2*)(smem + SM_WHI + off) = make_uint2(h0, h1);
            *(uint2*)(smem + SM_WLO + off) = make_uint2(l0, l1);
        }
        // ---- stage B (pre-split bf16 hi/lo from gmem, swizzled) ----
        #pragma unroll
        for (int i = 0; i < 4; ++i) {
            int idx = tid + 128 * i;               // 0..511
            int n = idx >> 4, s = idx & 15;
            size_t goff = (size_t)n * 4096 + (kc >> 1) + s * 4;
            uint4 vh = *(const uint4*)(Bh + goff);
            uint4 vl = *(const uint4*)(Bl + goff);
            unsigned off = (unsigned)(n * 256) + (((unsigned)s ^ (unsigned)(n & 7)) << 4);
            *(uint4*)(smem + SM_BHI + off) = vh;
            *(uint4*)(smem + SM_BLO + off) = vl;
        }
        __syncthreads();

        // ---- compute 8 k16 steps ----
        #pragma unroll
        for (int s = 0; s < 8; ++s) {
            unsigned aseg = (unsigned)(2 * s + acs);
            unsigned aoh = sb + SM_WHI + abase + ((aseg ^ (unsigned)arm) << 4);
            unsigned ah[4], al[4];
            ldsm4(ah[0], ah[1], ah[2], ah[3], aoh);
            ldsm4(al[0], al[1], al[2], al[3], aoh + (SM_WLO - SM_WHI));

            unsigned bseg = (unsigned)(2 * s + bcs);
            unsigned bo1 = sb + SM_BHI + (unsigned)(brow1 * 256)
                         + ((bseg ^ (unsigned)(brow1 & 7)) << 4);
            unsigned bo2 = sb + SM_BHI + (unsigned)(brow2 * 256)
                         + ((bseg ^ (unsigned)(brow2 & 7)) << 4);
            unsigned bh[8], bl[8];
            ldsm4(bh[0], bh[1], bh[2], bh[3], bo1);
            ldsm4(bh[4], bh[5], bh[6], bh[7], bo2);
            ldsm4(bl[0], bl[1], bl[2], bl[3], bo1 + (SM_BLO - SM_BHI));
            ldsm4(bl[4], bl[5], bl[6], bl[7], bo2 + (SM_BLO - SM_BHI));

            #pragma unroll
            for (int nt = 0; nt < 4; ++nt) {
                mma16816(acc[nt], ah, bh[2 * nt], bh[2 * nt + 1]);
                mma16816(acc[nt], al, bh[2 * nt], bh[2 * nt + 1]);
                mma16816(acc[nt], ah, bl[2 * nt], bl[2 * nt + 1]);
            }
        }
        __syncthreads();
    }

    // ---- epilogue: C[batch][wrow] plain stores ----
    int g = lane >> 2, t = lane & 3;
    int m = n0 + r0 + g;
    #pragma unroll
    for (int nt = 0; nt < 4; ++nt) {
        int col = nt * 8 + 2 * t;
        C[(size_t)col * ldc + m]           = acc[nt][0];
        C[(size_t)(col + 1) * ldc + m]     = acc[nt][1];
        C[(size_t)col * ldc + m + 8]       = acc[nt][2];
        C[(size_t)(col + 1) * ldc + m + 8] = acc[nt][3];
    }
}

// ---------------- RoPE (pairwise) ----------------
__global__ void rope_kernel(const float* __restrict__ rm) {
    int t = blockIdx.x * blockDim.x + threadIdx.x;   // 147456
    int p  = t & 63;
    int hr = t >> 6;
    int b  = hr / (H_ + KVH_);
    int hh = hr % (H_ + KVH_);
    float* ptr;
    if (hh < H_) ptr = g_qkv + (size_t)b * NTOT + hh * D_;
    else         ptr = g_qkv + (size_t)b * NTOT + HID_ + (hh - H_) * D_;
    float c = rm[(2 * p) * D_ + 2 * p];
    float s = rm[(2 * p + 1) * D_ + 2 * p];
    float e = ptr[2 * p], o = ptr[2 * p + 1];
    ptr[2 * p]     = fmaf(e, c,  o * s);
    ptr[2 * p + 1] = fmaf(o, c, -e * s);
}

// ---------------- attention ----------------
__global__ __launch_bounds__(256)
void attn_kernel(const float* __restrict__ cache_k,
                 const float* __restrict__ cache_v)
{
    int bidx = blockIdx.x;
    int b  = bidx >> 3;
    int kv = bidx & 7;
    int tid  = threadIdx.x;
    int r    = tid >> 5;
    int lane = tid & 31;

    __shared__ float sK[64][128];
    __shared__ float sS[8][512];

    const float scale = 0.0883883476483184405501055452631f;
    const float* qrow = g_qkv + (size_t)b * NTOT + (kv * 8 + r) * D_;
    float4 qv = *(const float4*)(qrow + lane * 4);
    qv.x *= scale; qv.y *= scale; qv.z *= scale; qv.w *= scale;

    const float* kb   = cache_k + ((size_t)(b * KVH_ + kv)) * CL_ * D_;
    const float* vb   = cache_v + ((size_t)(b * KVH_ + kv)) * CL_ * D_;
    const float* knew = g_qkv + (size_t)b * NTOT + HID_ + kv * D_;
    const float* vnew = g_qkv + (size_t)b * NTOT + HID_ + KVH_ * D_ + kv * D_;

    for (int c = 0; c < 8; ++c) {
        __syncthreads();
        #pragma unroll
        for (int i = 0; i < 8; ++i) {
            int v = tid + 256 * i;
            int j = v >> 5, dq = v & 31;
            int s = c * 64 + j;
            const float* src = (s == SP_) ? knew : (kb + (size_t)s * D_);
            *(float4*)&sK[j][dq * 4] = *(const float4*)(src + dq * 4);
        }
        __syncthreads();
        for (int j = 0; j < 64; ++j) {
            float4 k4 = *(const float4*)&sK[j][lane * 4];
            float p = qv.x * k4.x + qv.y * k4.y + qv.z * k4.z + qv.w * k4.w;
            #pragma unroll
            for (int o = 16; o; o >>= 1) p += __shfl_xor_sync(0xffffffffu, p, o);
            if (lane == 0) sS[r][c * 64 + j] = p;
        }
    }
    __syncthreads();

    float mx = -1e30f;
    #pragma unroll
    for (int i = 0; i < 16; ++i) mx = fmaxf(mx, sS[r][lane + 32 * i]);
    #pragma unroll
    for (int o = 16; o; o >>= 1) mx = fmaxf(mx, __shfl_xor_sync(0xffffffffu, mx, o));
    float sum = 0.0f;
    #pragma unroll
    for (int i = 0; i < 16; ++i) {
        float e = __expf(sS[r][lane + 32 * i] - mx);
        sS[r][lane + 32 * i] = e;
        sum += e;
    }
    #pragma unroll
    for (int o = 16; o; o >>= 1) sum += __shfl_xor_sync(0xffffffffu, sum, o);
    float inv = 1.0f / sum;
    #pragma unroll
    for (int i = 0; i < 16; ++i) sS[r][lane + 32 * i] *= inv;
    __syncthreads();

    float4 acc = make_float4(0.f, 0.f, 0.f, 0.f);
    for (int c = 0; c < 8; ++c) {
        __syncthreads();
        #pragma unroll
        for (int i = 0; i < 8; ++i) {
            int v = tid + 256 * i;
            int j = v >> 5, dq = v & 31;
            int s = c * 64 + j;
            const float* src = (s == SP_) ? vnew : (vb + (size_t)s * D_);
            *(float4*)&sK[j][dq * 4] = *(const float4*)(src + dq * 4);
        }
        __syncthreads();
        for (int j = 0; j < 64; ++j) {
            float pw = sS[r][c * 64 + j];
            float4 v4 = *(const float4*)&sK[j][lane * 4];
            acc.x = fmaf(pw, v4.x, acc.x);
            acc.y = fmaf(pw, v4.y, acc.y);
            acc.z = fmaf(pw, v4.z, acc.z);
            acc.w = fmaf(pw, v4.w, acc.w);
        }
    }
    // bf16 hi/lo split output for the wo GEMM (B operand layout [b][k/2])
    unsigned h0, l0, h1, l1;
    split2(acc.x, acc.y, h0, l0);
    split2(acc.z, acc.w, h1, l1);
    int h = kv * 8 + r;
    size_t wbase = (size_t)b * 4096 + h * 64 + lane * 2;
    g_ahi[wbase]     = h0;
    g_ahi[wbase + 1] = h1;
    g_alo[wbase]     = l0;
    g_alo[wbase + 1] = l1;
}

// ---------------- launcher ----------------
extern "C" void kernel_launch(void* const* d_in, const int* in_sizes, int n_in,
                              void* d_out, int out_size) {
    const float* x  = (const float*)d_in[0];
    const float* wq = (const float*)d_in[1];
    const float* wk = (const float*)d_in[2];
    const float* wv = (const float*)d_in[3];
    const float* wo = (const float*)d_in[4];
    const float* ck = (const float*)d_in[5];
    const float* cv = (const float*)d_in[6];
    const float* rm = (const float*)d_in[7];
    float* out = (float*)d_out;

    cudaFuncSetAttribute(gemm_mma, cudaFuncAttributeMaxDynamicSharedMemorySize, SM_TOT);

    // 1. split x into bf16 hi/lo
    cvt_x<<<512, 256>>>(x);

    // 2. fused QKV projection: 160 row-tiles of 64, full K, plain stores
    gemm_mma<<<160, 128, SM_TOT>>>(0, wq, wk, wv, 8192, 9216,
                                   0, nullptr, NTOT);

    // 3. RoPE on q and k
    rope_kernel<<<576, 256>>>(rm);

    // 4. attention (fp32 in, bf16 hi/lo out)
    attn_kernel<<<256, 256>>>(ck, cv);

    // 5. output projection: 128 row-tiles of 64, writes every d_out element once
    gemm_mma<<<128, 128, SM_TOT>>>(1, wo, wo, wo, 1 << 30, 1 << 30,
                                   1, out, HID_);
}

// round 7
// speedup vs baseline: 2.1206x; 2.1206x over previous
#include <cuda_runtime.h>
#include <cuda_bf16.h>

#define B_    32
#define H_    64
#define KVH_  8
#define D_    128
#define HID_  8192
#define CL_   1024
#define SP_   511
#define NTOT  10240

// ---------------- scratch ----------------
__device__ float    g_qkv[B_ * NTOT];       // fp32 qkv [b][n] (split-K accumulated)
__device__ unsigned g_xhi[B_ * 4096];       // x hi bf16x2 [b][k/2]
__device__ unsigned g_xlo[B_ * 4096];
__device__ unsigned g_ahi[B_ * 4096];       // attn out hi bf16x2 [b][k/2]
__device__ unsigned g_alo[B_ * 4096];
__device__ float    g_part[1024 * 8 * 132]; // attn partials [(b,kv,split)][head][128 acc + m + s]

// gemm smem layout (bytes): WHI[2]x16K, WLO[2]x16K, BHI[2]x8K, BLO[2]x8K
#define SMW_HI(buf) ((buf) * 16384)
#define SMW_LO(buf) (32768 + (buf) * 16384)
#define SMB_HI(buf) (65536 + (buf) * 8192)
#define SMB_LO(buf) (81920 + (buf) * 8192)
#define SM_TOT 98304

// ---------------- helpers ----------------
__device__ __forceinline__ void split2(float f0, float f1, unsigned& hi, unsigned& lo) {
    __nv_bfloat162 h = __floats2bfloat162_rn(f0, f1);
    unsigned hb = *reinterpret_cast<unsigned*>(&h);
    float h0 = __uint_as_float(hb << 16);
    float h1 = __uint_as_float(hb & 0xffff0000u);
    __nv_bfloat162 l = __floats2bfloat162_rn(f0 - h0, f1 - h1);
    hi = hb;
    lo = *reinterpret_cast<unsigned*>(&l);
}

__device__ __forceinline__ void ldsm4(unsigned& r0, unsigned& r1, unsigned& r2,
                                      unsigned& r3, unsigned addr) {
    asm volatile("ldmatrix.sync.aligned.m8n8.x4.shared.b16 {%0,%1,%2,%3}, [%4];"
                 : "=r"(r0), "=r"(r1), "=r"(r2), "=r"(r3) : "r"(addr));
}

__device__ __forceinline__ void mma16816(float* c, const unsigned* a,
                                         unsigned b0, unsigned b1) {
    asm volatile(
        "mma.sync.aligned.m16n8k16.row.col.f32.bf16.bf16.f32 "
        "{%0,%1,%2,%3}, {%4,%5,%6,%7}, {%8,%9}, {%0,%1,%2,%3};"
        : "+f"(c[0]), "+f"(c[1]), "+f"(c[2]), "+f"(c[3])
        : "r"(a[0]), "r"(a[1]), "r"(a[2]), "r"(a[3]), "r"(b0), "r"(b1));
}

// ---------------- zero + cvt ----------------
__global__ void zero_kernel(float* __restrict__ out) {
    const int n1 = B_ * NTOT;
    int t = blockIdx.x * blockDim.x + threadIdx.x;
    if (t < n1) g_qkv[t] = 0.0f;
    else if (t < n1 + B_ * HID_) out[t - n1] = 0.0f;
}

__global__ void cvt_x(const float* __restrict__ x) {
    int t = blockIdx.x * blockDim.x + threadIdx.x;      // 131072 pairs
    float f0 = x[2 * t], f1 = x[2 * t + 1];
    unsigned h, l;
    split2(f0, f1, h, l);
    g_xhi[t] = h;
    g_xlo[t] = l;
}

// ---------------- HMMA GEMM (BM=64, 8 warps, split-K=2, double-buffered) ----
// D[m=W-row][n=batch] = sum_k W[m][k]*B[n][k]; C[n][m] += (atomicAdd, 2-way).
__global__ __launch_bounds__(256)
void gemm_mma(int bsel,
              const float* __restrict__ W0, const float* __restrict__ W1,
              const float* __restrict__ W2,
              int nb1, int nb2,
              int csel, float* __restrict__ Cext, int ldc)
{
    extern __shared__ char smem[];
    unsigned sb = (unsigned)__cvta_generic_to_shared(smem);
    int tid = threadIdx.x, lane = tid & 31, wid = tid >> 5;

    int n0 = blockIdx.x * 64;
    const float* W; int wrow;
    if (n0 < nb1)      { W = W0; wrow = n0; }
    else if (n0 < nb2) { W = W1; wrow = n0 - nb1; }
    else               { W = W2; wrow = n0 - nb2; }

    const unsigned* __restrict__ Bh = bsel ? g_ahi : g_xhi;
    const unsigned* __restrict__ Bl = bsel ? g_alo : g_xlo;
    float* C = csel ? Cext : g_qkv;

    int kbase = blockIdx.y * (HID_ / 2);                // split-K=2
    const float* wbase = W + (size_t)wrow * HID_ + kbase;
    int kw0 = kbase >> 1;

    // warp tiling: 4 row-groups x 2 batch-halves
    int rg   = wid >> 1;
    int bh16 = wid & 1;

    // ldmatrix lane descriptors (layouts proven in R6)
    int arow = rg * 16 + (lane & 7) + ((lane >> 3) & 1) * 8;
    int acs  = (lane >> 4) & 1;
    int arm  = arow & 7;
    int brow = bh16 * 16 + (lane & 7) + ((lane >> 4) & 1) * 8;
    int bcs  = (lane >> 3) & 1;
    int brm  = brow & 7;

    float4 wreg[8];
    uint4  bhreg[2], blreg[2];

    float acc[2][4];
    #pragma unroll
    for (int i = 0; i < 2; ++i)
        #pragma unroll
        for (int j = 0; j < 4; ++j) acc[i][j] = 0.0f;

    // ---- load chunk c into registers ----
    #define LOADC(c) do {                                                        \
        const float* p_ = wbase + (c) * 128 + lane * 4;                          \
        _Pragma("unroll")                                                        \
        for (int i_ = 0; i_ < 8; ++i_)                                           \
            wreg[i_] = __ldcs((const float4*)(p_ + (size_t)(wid * 8 + i_) * HID_)); \
        _Pragma("unroll")                                                        \
        for (int i_ = 0; i_ < 2; ++i_) {                                         \
            int idx_ = tid + 256 * i_;                                           \
            int n_ = idx_ >> 4, s_ = idx_ & 15;                                  \
            size_t off_ = (size_t)n_ * 4096 + kw0 + (c) * 64 + s_ * 4;           \
            bhreg[i_] = *(const uint4*)(Bh + off_);                              \
            blreg[i_] = *(const uint4*)(Bl + off_);                              \
        }                                                                        \
    } while (0)

    // ---- store registers into smem buffer ----
    #define STOREC(buf) do {                                                     \
        _Pragma("unroll")                                                        \
        for (int i_ = 0; i_ < 8; ++i_) {                                         \
            int row_ = wid * 8 + i_;                                             \
            unsigned h0_, l0_, h1_, l1_;                                         \
            split2(wreg[i_].x, wreg[i_].y, h0_, l0_);                            \
            split2(wreg[i_].z, wreg[i_].w, h1_, l1_);                            \
            unsigned off_ = (unsigned)(row_ * 256)                               \
                          + ((((unsigned)lane >> 1) ^ (unsigned)(row_ & 7)) << 4)\
                          + (((unsigned)lane & 1u) << 3);                        \
            *(uint2*)(smem + SMW_HI(buf) + off_) = make_uint2(h0_, h1_);         \
            *(uint2*)(smem + SMW_LO(buf) + off_) = make_uint2(l0_, l1_);         \
        }                                                                        \
        _Pragma("unroll")                                                        \
        for (int i_ = 0; i_ < 2; ++i_) {                                         \
            int idx_ = tid + 256 * i_;                                           \
            int n_ = idx_ >> 4, s_ = idx_ & 15;                                  \
            unsigned off_ = (unsigned)(n_ * 256)                                 \
                          + (((unsigned)s_ ^ (unsigned)(n_ & 7)) << 4);          \
            *(uint4*)(smem + SMB_HI(buf) + off_) = bhreg[i_];                    \
            *(uint4*)(smem + SMB_LO(buf) + off_) = blreg[i_];                    \
        }                                                                        \
    } while (0)

    LOADC(0);
    STOREC(0);
    __syncthreads();

    const int NCH = (HID_ / 2) / 128;   // 32 chunks
    for (int c = 0; c < NCH; ++c) {
        int buf = c & 1;
        if (c + 1 < NCH) LOADC(c + 1);

        unsigned wh0 = sb + SMW_HI(buf), wl0 = sb + SMW_LO(buf);
        unsigned bb0 = sb + SMB_HI(buf), bl0 = sb + SMB_LO(buf);
        #pragma unroll
        for (int s = 0; s < 8; ++s) {
            unsigned aoff = (unsigned)(arow * 256)
                          + (((unsigned)(2 * s + acs) ^ (unsigned)arm) << 4);
            unsigned ah[4], al[4];
            ldsm4(ah[0], ah[1], ah[2], ah[3], wh0 + aoff);
            ldsm4(al[0], al[1], al[2], al[3], wl0 + aoff);
            unsigned boff = (unsigned)(brow * 256)
                          + (((unsigned)(2 * s + bcs) ^ (unsigned)brm) << 4);
            unsigned bh[4], bl[4];
            ldsm4(bh[0], bh[1], bh[2], bh[3], bb0 + boff);
            ldsm4(bl[0], bl[1], bl[2], bl[3], bl0 + boff);

            mma16816(acc[0], ah, bh[0], bh[1]);
            mma16816(acc[1], ah, bh[2], bh[3]);
            mma16816(acc[0], al, bh[0], bh[1]);
            mma16816(acc[1], al, bh[2], bh[3]);
            mma16816(acc[0], ah, bl[0], bl[1]);
            mma16816(acc[1], ah, bl[2], bl[3]);
        }

        if (c + 1 < NCH) STOREC((c + 1) & 1);
        __syncthreads();
    }

    // epilogue: split-K=2 accumulate
    int g = lane >> 2, t4 = lane & 3;
    int m = n0 + rg * 16 + g;
    #pragma unroll
    for (int nt = 0; nt < 2; ++nt) {
        int col = bh16 * 16 + nt * 8 + 2 * t4;
        atomicAdd(&C[(size_t)col * ldc + m],           acc[nt][0]);
        atomicAdd(&C[(size_t)(col + 1) * ldc + m],     acc[nt][1]);
        atomicAdd(&C[(size_t)col * ldc + m + 8],       acc[nt][2]);
        atomicAdd(&C[(size_t)(col + 1) * ldc + m + 8], acc[nt][3]);
    }
    #undef LOADC
    #undef STOREC
}

// ---------------- RoPE (pairwise) ----------------
__global__ void rope_kernel(const float* __restrict__ rm) {
    int t = blockIdx.x * blockDim.x + threadIdx.x;   // 147456
    int p  = t & 63;
    int hr = t >> 6;
    int b  = hr / (H_ + KVH_);
    int hh = hr % (H_ + KVH_);
    float* ptr;
    if (hh < H_) ptr = g_qkv + (size_t)b * NTOT + hh * D_;
    else         ptr = g_qkv + (size_t)b * NTOT + HID_ + (hh - H_) * D_;
    float c = rm[(2 * p) * D_ + 2 * p];
    float s = rm[(2 * p + 1) * D_ + 2 * p];
    float e = ptr[2 * p], o = ptr[2 * p + 1];
    ptr[2 * p]     = fmaf(e, c,  o * s);
    ptr[2 * p + 1] = fmaf(o, c, -e * s);
}

// ---------------- attention split (flash-decode, 4 splits x 128 pos) --------
__global__ __launch_bounds__(256)
void attn_split(const float* __restrict__ cache_k,
                const float* __restrict__ cache_v)
{
    int bidx  = blockIdx.x;            // ((b*8+kv)*4 + split), 0..1023
    int split = bidx & 3;
    int bk    = bidx >> 2;
    int b  = bk >> 3;
    int kv = bk & 7;
    int p0 = split * 128;

    int tid  = threadIdx.x;
    int r    = tid >> 5;
    int lane = tid & 31;

    __shared__ float sK[64][128];      // 32 KB chunk
    __shared__ float sS[8][128];       // 4 KB scores

    const float scale = 0.0883883476483184405501055452631f;
    const float* qrow = g_qkv + (size_t)b * NTOT + (kv * 8 + r) * D_;
    float4 qv = *(const float4*)(qrow + lane * 4);
    qv.x *= scale; qv.y *= scale; qv.z *= scale; qv.w *= scale;

    const float* kb   = cache_k + ((size_t)(b * KVH_ + kv)) * CL_ * D_;
    const float* vb   = cache_v + ((size_t)(b * KVH_ + kv)) * CL_ * D_;
    const float* knew = g_qkv + (size_t)b * NTOT + HID_ + kv * D_;
    const float* vnew = g_qkv + (size_t)b * NTOT + HID_ + KVH_ * D_ + kv * D_;

    // -------- scores --------
    for (int c = 0; c < 2; ++c) {
        __syncthreads();
        #pragma unroll
        for (int i = 0; i < 8; ++i) {
            int v = tid + 256 * i;
            int j = v >> 5, dq = v & 31;
            int s = p0 + c * 64 + j;
            const float* src = (s == SP_) ? (knew + dq * 4) : (kb + (size_t)s * D_ + dq * 4);
            *(float4*)&sK[j][dq * 4] = (s == SP_) ? *(const float4*)src
                                                  : __ldcs((const float4*)src);
        }
        __syncthreads();
        for (int j = 0; j < 64; ++j) {
            float4 k4 = *(const float4*)&sK[j][lane * 4];
            float p = qv.x * k4.x + qv.y * k4.y + qv.z * k4.z + qv.w * k4.w;
            #pragma unroll
            for (int o = 16; o; o >>= 1) p += __shfl_xor_sync(0xffffffffu, p, o);
            if (lane == 0) sS[r][c * 64 + j] = p;
        }
    }
    __syncthreads();

    // -------- partial softmax (unnormalized) --------
    float mx = -1e30f;
    #pragma unroll
    for (int i = 0; i < 4; ++i) mx = fmaxf(mx, sS[r][lane + 32 * i]);
    #pragma unroll
    for (int o = 16; o; o >>= 1) mx = fmaxf(mx, __shfl_xor_sync(0xffffffffu, mx, o));
    float sum = 0.0f;
    #pragma unroll
    for (int i = 0; i < 4; ++i) {
        float e = __expf(sS[r][lane + 32 * i] - mx);
        sS[r][lane + 32 * i] = e;
        sum += e;
    }
    #pragma unroll
    for (int o = 16; o; o >>= 1) sum += __shfl_xor_sync(0xffffffffu, sum, o);

    // -------- probs @ V (unnormalized acc) --------
    float4 acc = make_float4(0.f, 0.f, 0.f, 0.f);
    for (int c = 0; c < 2; ++c) {
        __syncthreads();
        #pragma unroll
        for (int i = 0; i < 8; ++i) {
            int v = tid + 256 * i;
            int j = v >> 5, dq = v & 31;
            int s = p0 + c * 64 + j;
            const float* src = (s == SP_) ? (vnew + dq * 4) : (vb + (size_t)s * D_ + dq * 4);
            *(float4*)&sK[j][dq * 4] = (s == SP_) ? *(const float4*)src
                                                  : __ldcs((const float4*)src);
        }
        __syncthreads();
        for (int j = 0; j < 64; ++j) {
            float pw = sS[r][c * 64 + j];
            float4 v4 = *(const float4*)&sK[j][lane * 4];
            acc.x = fmaf(pw, v4.x, acc.x);
            acc.y = fmaf(pw, v4.y, acc.y);
            acc.z = fmaf(pw, v4.z, acc.z);
            acc.w = fmaf(pw, v4.w, acc.w);
        }
    }

    float* p = g_part + ((size_t)bidx * 8 + r) * 132;
    *(float4*)(p + lane * 4) = acc;
    if (lane == 0) { p[128] = mx; p[129] = sum; }
}

// ---------------- combine partials -> bf16 hi/lo attn output ----------------
__global__ __launch_bounds__(256)
void combine_attn() {
    int w = blockIdx.x * 8 + (threadIdx.x >> 5);   // 0..2047 = (b,h)
    int lane = threadIdx.x & 31;
    int b = w >> 6, h = w & 63;
    int kv = h >> 3, r = h & 7;

    float m[4], s[4];
    float4 a[4];
    #pragma unroll
    for (int i = 0; i < 4; ++i) {
        const float* p = g_part + ((size_t)((b * 8 + kv) * 4 + i) * 8 + r) * 132;
        a[i] = *(const float4*)(p + lane * 4);
        m[i] = p[128];
        s[i] = p[129];
    }
    float M = fmaxf(fmaxf(m[0], m[1]), fmaxf(m[2], m[3]));
    float wsum = 0.0f;
    float4 o = make_float4(0.f, 0.f, 0.f, 0.f);
    #pragma unroll
    for (int i = 0; i < 4; ++i) {
        float wi = __expf(m[i] - M);
        wsum += wi * s[i];
        o.x = fmaf(wi, a[i].x, o.x);
        o.y = fmaf(wi, a[i].y, o.y);
        o.z = fmaf(wi, a[i].z, o.z);
        o.w = fmaf(wi, a[i].w, o.w);
    }
    float inv = 1.0f / wsum;
    o.x *= inv; o.y *= inv; o.z *= inv; o.w *= inv;

    unsigned h0, l0, h1, l1;
    split2(o.x, o.y, h0, l0);
    split2(o.z, o.w, h1, l1);
    size_t wb = (size_t)b * 4096 + h * 64 + lane * 2;
    g_ahi[wb]     = h0;
    g_ahi[wb + 1] = h1;
    g_alo[wb]     = l0;
    g_alo[wb + 1] = l1;
}

// ---------------- launcher ----------------
extern "C" void kernel_launch(void* const* d_in, const int* in_sizes, int n_in,
                              void* d_out, int out_size) {
    const float* x  = (const float*)d_in[0];
    const float* wq = (const float*)d_in[1];
    const float* wk = (const float*)d_in[2];
    const float* wv = (const float*)d_in[3];
    const float* wo = (const float*)d_in[4];
    const float* ck = (const float*)d_in[5];
    const float* cv = (const float*)d_in[6];
    const float* rm = (const float*)d_in[7];
    float* out = (float*)d_out;

    cudaFuncSetAttribute(gemm_mma, cudaFuncAttributeMaxDynamicSharedMemorySize, SM_TOT);

    // 1. zero split-K accumulators (g_qkv + d_out)
    zero_kernel<<<2304, 256>>>(out);

    // 2. split x into bf16 hi/lo
    cvt_x<<<512, 256>>>(x);

    // 3. fused QKV projection: 160 row-tiles x split-K 2
    gemm_mma<<<dim3(160, 2), 256, SM_TOT>>>(0, wq, wk, wv, 8192, 9216,
                                            0, nullptr, NTOT);

    // 4. RoPE on q and k
    rope_kernel<<<576, 256>>>(rm);

    // 5. attention: 4-way flash-decode split + combine
    attn_split<<<1024, 256>>>(ck, cv);
    combine_attn<<<256, 256>>>();

    // 6. output projection: 128 row-tiles x split-K 2 into d_out
    gemm_mma<<<dim3(128, 2), 256, SM_TOT>>>(1, wo, wo, wo, 1 << 30, 1 << 30,
                                            1, out, HID_);
}

// round 9
// speedup vs baseline: 2.7946x; 1.3178x over previous
#include <cuda_runtime.h>
#include <cuda_bf16.h>

#define B_    32
#define H_    64
#define KVH_  8
#define D_    128
#define HID_  8192
#define CL_   1024
#define SP_   511
#define NTOT  10240

// ---------------- scratch ----------------
__device__ float    g_qkv[B_ * NTOT];       // fp32 qkv [b][n] (split-K accumulated)
__device__ unsigned g_xhi[B_ * 4096];       // x hi bf16x2 [b][k/2]
__device__ unsigned g_xlo[B_ * 4096];
__device__ unsigned g_ahi[B_ * 4096];       // attn out hi bf16x2 [b][k/2]
__device__ unsigned g_alo[B_ * 4096];
__device__ float    g_part[2048 * 8 * 132]; // attn partials [(b,kv,split)][head][128 acc + m + s]

// gemm smem (48 KB): WHI[2]x8K, WLO[2]x8K, BHI[2]x4K, BLO[2]x4K
#define SMW_HI(buf) ((buf) * 8192)
#define SMW_LO(buf) (16384 + (buf) * 8192)
#define SMB_HI(buf) (32768 + (buf) * 4096)
#define SMB_LO(buf) (40960 + (buf) * 4096)
#define SM_TOT 49152

// ---------------- helpers ----------------
__device__ __forceinline__ void split2(float f0, float f1, unsigned& hi, unsigned& lo) {
    __nv_bfloat162 h = __floats2bfloat162_rn(f0, f1);
    unsigned hb = *reinterpret_cast<unsigned*>(&h);
    float h0 = __uint_as_float(hb << 16);
    float h1 = __uint_as_float(hb & 0xffff0000u);
    __nv_bfloat162 l = __floats2bfloat162_rn(f0 - h0, f1 - h1);
    hi = hb;
    lo = *reinterpret_cast<unsigned*>(&l);
}

__device__ __forceinline__ void ldsm4(unsigned& r0, unsigned& r1, unsigned& r2,
                                      unsigned& r3, unsigned addr) {
    asm volatile("ldmatrix.sync.aligned.m8n8.x4.shared.b16 {%0,%1,%2,%3}, [%4];"
                 : "=r"(r0), "=r"(r1), "=r"(r2), "=r"(r3) : "r"(addr));
}

__device__ __forceinline__ void mma16816(float* c, const unsigned* a,
                                         unsigned b0, unsigned b1) {
    asm volatile(
        "mma.sync.aligned.m16n8k16.row.col.f32.bf16.bf16.f32 "
        "{%0,%1,%2,%3}, {%4,%5,%6,%7}, {%8,%9}, {%0,%1,%2,%3};"
        : "+f"(c[0]), "+f"(c[1]), "+f"(c[2]), "+f"(c[3])
        : "r"(a[0]), "r"(a[1]), "r"(a[2]), "r"(a[3]), "r"(b0), "r"(b1));
}

// ---------------- zero + cvt ----------------
__global__ void zero_kernel(float* __restrict__ out) {
    const int n1 = B_ * NTOT;
    int t = blockIdx.x * blockDim.x + threadIdx.x;
    if (t < n1) g_qkv[t] = 0.0f;
    else if (t < n1 + B_ * HID_) out[t - n1] = 0.0f;
}

__global__ void cvt_x(const float* __restrict__ x) {
    int t = blockIdx.x * blockDim.x + threadIdx.x;      // 131072 pairs
    float f0 = x[2 * t], f1 = x[2 * t + 1];
    unsigned h, l;
    split2(f0, f1, h, l);
    g_xhi[t] = h;
    g_xlo[t] = l;
}

// ---------------- HMMA GEMM (BM=64, Kchunk=64, 8 warps, split-K=4) ----------
// D[m=W-row][n=batch] = sum_k W[m][k]*B[n][k]; C[n][m] += (atomicAdd).
__global__ __launch_bounds__(256, 4)
void gemm_mma(int bsel,
              const float* __restrict__ W0, const float* __restrict__ W1,
              const float* __restrict__ W2,
              int nb1, int nb2,
              int csel, float* __restrict__ Cext, int ldc)
{
    extern __shared__ char smem[];
    unsigned sb = (unsigned)__cvta_generic_to_shared(smem);
    int tid = threadIdx.x, lane = tid & 31, wid = tid >> 5;

    int n0 = blockIdx.x * 64;
    const float* W; int wrow;
    if (n0 < nb1)      { W = W0; wrow = n0; }
    else if (n0 < nb2) { W = W1; wrow = n0 - nb1; }
    else               { W = W2; wrow = n0 - nb2; }

    const unsigned* __restrict__ Bh = bsel ? g_ahi : g_xhi;
    const unsigned* __restrict__ Bl = bsel ? g_alo : g_xlo;
    float* C = csel ? Cext : g_qkv;

    int kbase = blockIdx.y * (HID_ / 4);                // split-K=4
    const float* wbase = W + (size_t)wrow * HID_ + kbase;
    int kw0 = kbase >> 1;

    // warp tiling: 4 row-groups x 2 batch-halves
    int rg   = wid >> 1;
    int bh16 = wid & 1;

    // ldmatrix lane descriptors (row stride 128B = 8 segs)
    int arow = rg * 16 + (lane & 7) + ((lane >> 3) & 1) * 8;
    int acs  = (lane >> 4) & 1;
    int arm  = arow & 7;
    int brow = bh16 * 16 + (lane & 7) + ((lane >> 4) & 1) * 8;
    int bcs  = (lane >> 3) & 1;
    int brm  = brow & 7;

    float4 wreg[4];
    uint4  bhreg, blreg;

    float acc[2][4];
    #pragma unroll
    for (int i = 0; i < 2; ++i)
        #pragma unroll
        for (int j = 0; j < 4; ++j) acc[i][j] = 0.0f;

    #define LOADC(c) do {                                                        \
        _Pragma("unroll")                                                        \
        for (int i_ = 0; i_ < 4; ++i_) {                                         \
            int idx_ = tid + 256 * i_;                                           \
            int row_ = idx_ >> 4, kq_ = idx_ & 15;                               \
            wreg[i_] = __ldcs((const float4*)(wbase + (c) * 64                   \
                              + (size_t)row_ * HID_ + kq_ * 4));                 \
        }                                                                        \
        {                                                                        \
            int n_ = tid >> 3, s_ = tid & 7;                                     \
            size_t off_ = (size_t)n_ * 4096 + kw0 + (c) * 32 + s_ * 4;           \
            bhreg = *(const uint4*)(Bh + off_);                                  \
            blreg = *(const uint4*)(Bl + off_);                                  \
        }                                                                        \
    } while (0)

    #define STOREC(buf) do {                                                     \
        _Pragma("unroll")                                                        \
        for (int i_ = 0; i_ < 4; ++i_) {                                         \
            int idx_ = tid + 256 * i_;                                           \
            int row_ = idx_ >> 4, kq_ = idx_ & 15;                               \
            unsigned h0_, l0_, h1_, l1_;                                         \
            split2(wreg[i_].x, wreg[i_].y, h0_, l0_);                            \
            split2(wreg[i_].z, wreg[i_].w, h1_, l1_);                            \
            unsigned off_ = (unsigned)(row_ * 128)                               \
                          + ((((unsigned)kq_ >> 1) ^ (unsigned)(row_ & 7)) << 4) \
                          + (((unsigned)kq_ & 1u) << 3);                         \
            *(uint2*)(smem + SMW_HI(buf) + off_) = make_uint2(h0_, h1_);         \
            *(uint2*)(smem + SMW_LO(buf) + off_) = make_uint2(l0_, l1_);         \
        }                                                                        \
        {                                                                        \
            int n_ = tid >> 3, s_ = tid & 7;                                     \
            unsigned off_ = (unsigned)(n_ * 128)                                 \
                          + (((unsigned)s_ ^ (unsigned)(n_ & 7)) << 4);          \
            *(uint4*)(smem + SMB_HI(buf) + off_) = bhreg;                        \
            *(uint4*)(smem + SMB_LO(buf) + off_) = blreg;                        \
        }                                                                        \
    } while (0)

    LOADC(0);
    STOREC(0);
    __syncthreads();

    const int NCH = (HID_ / 4) / 64;    // 32 chunks
    for (int c = 0; c < NCH; ++c) {
        int buf = c & 1;
        if (c + 1 < NCH) LOADC(c + 1);

        unsigned wh0 = sb + SMW_HI(buf), wl0 = sb + SMW_LO(buf);
        unsigned bb0 = sb + SMB_HI(buf), bl0 = sb + SMB_LO(buf);
        #pragma unroll
        for (int s = 0; s < 4; ++s) {
            unsigned aoff = (unsigned)(arow * 128)
                          + (((unsigned)(2 * s + acs) ^ (unsigned)arm) << 4);
            unsigned ah[4], al[4];
            ldsm4(ah[0], ah[1], ah[2], ah[3], wh0 + aoff);
            ldsm4(al[0], al[1], al[2], al[3], wl0 + aoff);
            unsigned boff = (unsigned)(brow * 128)
                          + (((unsigned)(2 * s + bcs) ^ (unsigned)brm) << 4);
            unsigned bh[4], bl[4];
            ldsm4(bh[0], bh[1], bh[2], bh[3], bb0 + boff);
            ldsm4(bl[0], bl[1], bl[2], bl[3], bl0 + boff);

            mma16816(acc[0], ah, bh[0], bh[1]);
            mma16816(acc[1], ah, bh[2], bh[3]);
            mma16816(acc[0], al, bh[0], bh[1]);
            mma16816(acc[1], al, bh[2], bh[3]);
            mma16816(acc[0], ah, bl[0], bl[1]);
            mma16816(acc[1], ah, bl[2], bl[3]);
        }

        if (c + 1 < NCH) STOREC((c + 1) & 1);
        __syncthreads();
    }

    // epilogue: split-K accumulate
    int g = lane >> 2, t4 = lane & 3;
    int m = n0 + rg * 16 + g;
    #pragma unroll
    for (int nt = 0; nt < 2; ++nt) {
        int col = bh16 * 16 + nt * 8 + 2 * t4;
        atomicAdd(&C[(size_t)col * ldc + m],           acc[nt][0]);
        atomicAdd(&C[(size_t)(col + 1) * ldc + m],     acc[nt][1]);
        atomicAdd(&C[(size_t)col * ldc + m + 8],       acc[nt][2]);
        atomicAdd(&C[(size_t)(col + 1) * ldc + m + 8], acc[nt][3]);
    }
    #undef LOADC
    #undef STOREC
}

// ---------------- RoPE (pairwise) ----------------
__global__ void rope_kernel(const float* __restrict__ rm) {
    int t = blockIdx.x * blockDim.x + threadIdx.x;   // 147456
    int p  = t & 63;
    int hr = t >> 6;
    int b  = hr / (H_ + KVH_);
    int hh = hr % (H_ + KVH_);
    float* ptr;
    if (hh < H_) ptr = g_qkv + (size_t)b * NTOT + hh * D_;
    else         ptr = g_qkv + (size_t)b * NTOT + HID_ + (hh - H_) * D_;
    float c = rm[(2 * p) * D_ + 2 * p];
    float s = rm[(2 * p + 1) * D_ + 2 * p];
    float e = ptr[2 * p], o = ptr[2 * p + 1];
    ptr[2 * p]     = fmaf(e, c,  o * s);
    ptr[2 * p + 1] = fmaf(o, c, -e * s);
}

// ---------------- attention split (8 splits x 64 pos, shuffle-free) ---------
__global__ __launch_bounds__(256)
void attn_split(const float* __restrict__ cache_k,
                const float* __restrict__ cache_v)
{
    int bidx  = blockIdx.x;            // ((b*8+kv)*8 + split), 0..2047
    int split = bidx & 7;
    int bk    = bidx >> 3;
    int b  = bk >> 3;
    int kv = bk & 7;
    int p0 = split * 64;

    int tid  = threadIdx.x;
    int r    = tid >> 5;
    int lane = tid & 31;

    __shared__ float sQ[8][128];       // 4 KB (pre-scaled q)
    __shared__ float sK[64][128];      // 32 KB, column-XOR swizzled
    __shared__ float sP[8][64];        // 2 KB probs

    const float scale = 0.0883883476483184405501055452631f;

    const float* kb   = cache_k + ((size_t)(b * KVH_ + kv)) * CL_ * D_;
    const float* vb   = cache_v + ((size_t)(b * KVH_ + kv)) * CL_ * D_;
    const float* knew = g_qkv + (size_t)b * NTOT + HID_ + kv * D_;
    const float* vnew = g_qkv + (size_t)b * NTOT + HID_ + KVH_ * D_ + kv * D_;

    // stage q (scaled)
    {
        int h = tid >> 5, part = tid & 31;
        float4 q = *(const float4*)(g_qkv + (size_t)b * NTOT + (kv * 8 + h) * D_ + part * 4);
        q.x *= scale; q.y *= scale; q.z *= scale; q.w *= scale;
        *(float4*)&sQ[h][part * 4] = q;
    }
    // stage K (swizzled: seg' = dq ^ (j & 31))
    #pragma unroll
    for (int i = 0; i < 8; ++i) {
        int v = tid + 256 * i;
        int j = v >> 5, dq = v & 31;
        int s = p0 + j;
        float4 kd = (s == SP_) ? *(const float4*)(knew + dq * 4)
                               : __ldcs((const float4*)(kb + (size_t)s * D_ + dq * 4));
        *(float4*)&sK[j][(dq ^ (j & 31)) << 2] = kd;
    }
    __syncthreads();

    // phase 1: lane computes full dots for positions j1=lane, j2=lane+32
    float s1 = 0.0f, s2 = 0.0f;
    #pragma unroll
    for (int c = 0; c < 32; ++c) {
        float4 qc = *(const float4*)&sQ[r][c * 4];
        float4 k1 = *(const float4*)&sK[lane][(c ^ lane) << 2];
        float4 k2 = *(const float4*)&sK[lane + 32][(c ^ lane) << 2];
        s1 = fmaf(qc.x, k1.x, fmaf(qc.y, k1.y, fmaf(qc.z, k1.z, fmaf(qc.w, k1.w, s1))));
        s2 = fmaf(qc.x, k2.x, fmaf(qc.y, k2.y, fmaf(qc.z, k2.z, fmaf(qc.w, k2.w, s2))));
    }

    // phase 2: partial softmax in registers
    float mx = fmaxf(s1, s2);
    #pragma unroll
    for (int o = 16; o; o >>= 1) mx = fmaxf(mx, __shfl_xor_sync(0xffffffffu, mx, o));
    float e1 = __expf(s1 - mx), e2 = __expf(s2 - mx);
    float sum = e1 + e2;
    #pragma unroll
    for (int o = 16; o; o >>= 1) sum += __shfl_xor_sync(0xffffffffu, sum, o);
    sP[r][lane]      = e1;
    sP[r][lane + 32] = e2;

    // stage V over K
    __syncthreads();
    #pragma unroll
    for (int i = 0; i < 8; ++i) {
        int v = tid + 256 * i;
        int j = v >> 5, dq = v & 31;
        int s = p0 + j;
        float4 vd = (s == SP_) ? *(const float4*)(vnew + dq * 4)
                               : __ldcs((const float4*)(vb + (size_t)s * D_ + dq * 4));
        *(float4*)&sK[j][(dq ^ (j & 31)) << 2] = vd;
    }
    __syncthreads();

    // phase 3: acc = sum_j p_j * V[j][lane*4..]
    float4 acc = make_float4(0.f, 0.f, 0.f, 0.f);
    #pragma unroll 8
    for (int j = 0; j < 64; ++j) {
        float pw = sP[r][j];
        float4 v4 = *(const float4*)&sK[j][(lane ^ (j & 31)) << 2];
        acc.x = fmaf(pw, v4.x, acc.x);
        acc.y = fmaf(pw, v4.y, acc.y);
        acc.z = fmaf(pw, v4.z, acc.z);
        acc.w = fmaf(pw, v4.w, acc.w);
    }

    float* p = g_part + ((size_t)bidx * 8 + r) * 132;
    *(float4*)(p + lane * 4) = acc;
    if (lane == 0) { p[128] = mx; p[129] = sum; }
}

// ---------------- combine partials -> bf16 hi/lo attn output ----------------
__global__ __launch_bounds__(256)
void combine_attn() {
    int w = blockIdx.x * 8 + (threadIdx.x >> 5);   // 0..2047 = (b,h)
    int lane = threadIdx.x & 31;
    int b = w >> 6, h = w & 63;
    int kv = h >> 3, r = h & 7;

    float m[8], s[8];
    float4 a[8];
    #pragma unroll
    for (int i = 0; i < 8; ++i) {
        const float* p = g_part + ((size_t)((b * 8 + kv) * 8 + i) * 8 + r) * 132;
        a[i] = *(const float4*)(p + lane * 4);
        m[i] = p[128];
        s[i] = p[129];
    }
    float M = m[0];
    #pragma unroll
    for (int i = 1; i < 8; ++i) M = fmaxf(M, m[i]);
    float wsum = 0.0f;
    float4 o = make_float4(0.f, 0.f, 0.f, 0.f);
    #pragma unroll
    for (int i = 0; i < 8; ++i) {
        float wi = __expf(m[i] - M);
        wsum += wi * s[i];
        o.x = fmaf(wi, a[i].x, o.x);
        o.y = fmaf(wi, a[i].y, o.y);
        o.z = fmaf(wi, a[i].z, o.z);
        o.w = fmaf(wi, a[i].w, o.w);
    }
    float inv = 1.0f / wsum;
    o.x *= inv; o.y *= inv; o.z *= inv; o.w *= inv;

    unsigned h0, l0, h1, l1;
    split2(o.x, o.y, h0, l0);
    split2(o.z, o.w, h1, l1);
    size_t wb = (size_t)b * 4096 + h * 64 + lane * 2;
    g_ahi[wb]     = h0;
    g_ahi[wb + 1] = h1;
    g_alo[wb]     = l0;
    g_alo[wb + 1] = l1;
}

// ---------------- launcher ----------------
extern "C" void kernel_launch(void* const* d_in, const int* in_sizes, int n_in,
                              void* d_out, int out_size) {
    const float* x  = (const float*)d_in[0];
    const float* wq = (const float*)d_in[1];
    const float* wk = (const float*)d_in[2];
    const float* wv = (const float*)d_in[3];
    const float* wo = (const float*)d_in[4];
    const float* ck = (const float*)d_in[5];
    const float* cv = (const float*)d_in[6];
    const float* rm = (const float*)d_in[7];
    float* out = (float*)d_out;

    cudaFuncSetAttribute(gemm_mma, cudaFuncAttributeMaxDynamicSharedMemorySize, SM_TOT);

    // 1. zero split-K accumulators (g_qkv + d_out)
    zero_kernel<<<2304, 256>>>(out);

    // 2. split x into bf16 hi/lo
    cvt_x<<<512, 256>>>(x);

    // 3. fused QKV projection: 160 row-tiles x split-K 4
    gemm_mma<<<dim3(160, 4), 256, SM_TOT>>>(0, wq, wk, wv, 8192, 9216,
                                            0, nullptr, NTOT);

    // 4. RoPE on q and k
    rope_kernel<<<576, 256>>>(rm);

    // 5. attention: 8-way flash-decode split + combine
    attn_split<<<2048, 256>>>(ck, cv);
    combine_attn<<<256, 256>>>();

    // 6. output projection: 128 row-tiles x split-K 4 into d_out
    gemm_mma<<<dim3(128, 4), 256, SM_TOT>>>(1, wo, wo, wo, 1 << 30, 1 << 30,
                                            1, out, HID_);
}